// round 2
// baseline (speedup 1.0000x reference)
#include <cuda_runtime.h>

#define DIM 96
#define DIM3 (DIM*DIM*DIM)            /* 884736 */
#define C 24
#define N_CUR 150000
#define N_GLOB 200000
#define N_TGT_LOC 100000
#define N_TGT_GLOB 120000
#define N_TGT (N_TGT_LOC + N_TGT_GLOB)   /* 220000 */

/* output layout (float32, concat of reference return tuple) */
#define OFF_COORDS 0
#define OFF_CURVOL (N_CUR*3)                      /* 450000 */
#define OFF_GLOBVOL (OFF_CURVOL + DIM3*C)         /* 21683664 */
#define OFF_TGTVOL (OFF_GLOBVOL + DIM3*C)         /* 42917328 */
#define OFF_VALID  (OFF_TGTVOL + DIM3)            /* 43802064 */
#define OFF_VALIDT (OFF_VALID + N_GLOB)           /* 44002064 */
/* total = 44122064 */

__device__ int g_win_cur[DIM3];
__device__ int g_win_glob[DIM3];
__device__ int g_win_tgt[DIM3];

__device__ __forceinline__ int voxel(int x, int y, int z) {
    return (x * DIM + y) * DIM + z;
}

/* ---- 1. init: zero volumes, ones target, -1 winners, coords copy ---- */
__global__ void k_init(float* __restrict__ out, const int* __restrict__ cur_coords) {
    int i = blockIdx.x * blockDim.x + threadIdx.x;
    const int NV4 = (DIM3 * C) / 4;        /* 5308416 */
    if (i < NV4) {
        float4 z = make_float4(0.f, 0.f, 0.f, 0.f);
        ((float4*)(out + OFF_CURVOL))[i]  = z;
        ((float4*)(out + OFF_GLOBVOL))[i] = z;
    }
    if (i < DIM3 / 4) {
        float4 one = make_float4(1.f, 1.f, 1.f, 1.f);
        ((float4*)(out + OFF_TGTVOL))[i] = one;
        int4 neg = make_int4(-1, -1, -1, -1);
        ((int4*)g_win_cur)[i]  = neg;
        ((int4*)g_win_glob)[i] = neg;
        ((int4*)g_win_tgt)[i]  = neg;
    }
    if (i < (N_CUR * 3) / 4) {             /* 112500 */
        int4 c = ((const int4*)cur_coords)[i];
        ((float4*)(out + OFF_COORDS))[i] =
            make_float4((float)c.x, (float)c.y, (float)c.z, (float)c.w);
    }
}

/* ---- 2. fused winners: current (last wins) + target (global then local) ---- */
__global__ void k_win_cur_tgt(const int* __restrict__ cc,
                              const int* __restrict__ gtraw,
                              const int* __restrict__ loc,
                              const int* __restrict__ org,
                              float* __restrict__ out) {
    int i = blockIdx.x * blockDim.x + threadIdx.x;
    /* current winners */
    if (i < N_CUR) {
        int x = cc[3*i], y = cc[3*i+1], z = cc[3*i+2];
        if ((unsigned)x < DIM && (unsigned)y < DIM && (unsigned)z < DIM)
            atomicMax(&g_win_cur[voxel(x, y, z)], i);
    }
    /* target winners */
    if (i < N_TGT) {
        if (i < N_TGT_GLOB) {
            int x = gtraw[3*i]   - org[0];
            int y = gtraw[3*i+1] - org[1];
            int z = gtraw[3*i+2] - org[2];
            bool inb = (unsigned)x < DIM && (unsigned)y < DIM && (unsigned)z < DIM;
            out[OFF_VALIDT + i] = inb ? 1.f : 0.f;
            if (inb) atomicMax(&g_win_tgt[voxel(x, y, z)], i);
        } else {
            int j = i - N_TGT_GLOB;
            int x = loc[3*j], y = loc[3*j+1], z = loc[3*j+2];
            if ((unsigned)x < DIM && (unsigned)y < DIM && (unsigned)z < DIM)
                atomicMax(&g_win_tgt[voxel(x, y, z)], i);
        }
    }
}

/* ---- 3. global winners: needs occupancy (= g_win_cur >= 0) ---- */
__global__ void k_win_glob(const int* __restrict__ graw,
                           const int* __restrict__ org,
                           float* __restrict__ out) {
    int i = blockIdx.x * blockDim.x + threadIdx.x;
    if (i >= N_GLOB) return;
    int x = graw[3*i]   - org[0];
    int y = graw[3*i+1] - org[1];
    int z = graw[3*i+2] - org[2];
    bool inb = (unsigned)x < DIM && (unsigned)y < DIM && (unsigned)z < DIM;
    int cx = min(max(x, 0), DIM-1);
    int cy = min(max(y, 0), DIM-1);
    int cz = min(max(z, 0), DIM-1);
    bool occ = g_win_cur[voxel(cx, cy, cz)] >= 0;
    bool valid = inb && occ;
    out[OFF_VALID + i] = valid ? 1.f : 0.f;
    if (valid) atomicMax(&g_win_glob[voxel(x, y, z)], i);
}

/* ---- 4. fused winner-gated 24-ch writes (cur then glob), float4 x6 ---- */
__global__ void k_write_vols(const int* __restrict__ cc,
                             const float* __restrict__ cvals,
                             const int* __restrict__ graw,
                             const int* __restrict__ org,
                             const float* __restrict__ gvals,
                             float* __restrict__ out) {
    int t = blockIdx.x * blockDim.x + threadIdx.x;
    if (t < N_CUR * 6) {
        int p = t / 6, q = t % 6;
        int x = cc[3*p], y = cc[3*p+1], z = cc[3*p+2];
        if ((unsigned)x < DIM && (unsigned)y < DIM && (unsigned)z < DIM) {
            int v = voxel(x, y, z);
            if (g_win_cur[v] == p) {
                float4 w = ((const float4*)(cvals + p*C))[q];
                ((float4*)(out + OFF_CURVOL + (long long)v * C))[q] = w;
            }
        }
        return;
    }
    int t2 = t - N_CUR * 6;
    if (t2 >= N_GLOB * 6) return;
    int p = t2 / 6, q = t2 % 6;
    int x = graw[3*p]   - org[0];
    int y = graw[3*p+1] - org[1];
    int z = graw[3*p+2] - org[2];
    if (!((unsigned)x < DIM && (unsigned)y < DIM && (unsigned)z < DIM)) return;
    int v = voxel(x, y, z);
    if (g_win_glob[v] != p) return;
    float4 w = ((const float4*)(gvals + p*C))[q];
    ((float4*)(out + OFF_GLOBVOL + (long long)v * C))[q] = w;
}

/* ---- 5. target TSDF write ---- */
__global__ void k_write_tgt(const int* __restrict__ gtraw,
                            const int* __restrict__ loc,
                            const int* __restrict__ org,
                            const float* __restrict__ gtsdf,
                            const float* __restrict__ ltsdf,
                            float* __restrict__ out) {
    int i = blockIdx.x * blockDim.x + threadIdx.x;
    if (i >= N_TGT) return;
    int x, y, z;
    float val;
    if (i < N_TGT_GLOB) {
        x = gtraw[3*i]   - org[0];
        y = gtraw[3*i+1] - org[1];
        z = gtraw[3*i+2] - org[2];
        val = gtsdf[i];
    } else {
        int j = i - N_TGT_GLOB;
        x = loc[3*j]; y = loc[3*j+1]; z = loc[3*j+2];
        val = ltsdf[j];
    }
    if (!((unsigned)x < DIM && (unsigned)y < DIM && (unsigned)z < DIM)) return;
    int v = voxel(x, y, z);
    if (g_win_tgt[v] == i)
        out[OFF_TGTVOL + v] = val;
}

extern "C" void kernel_launch(void* const* d_in, const int* in_sizes, int n_in,
                              void* d_out, int out_size) {
    const int*   cur_coords = (const int*)  d_in[0];
    const float* cur_vals   = (const float*)d_in[1];
    const int*   glob_raw   = (const int*)  d_in[2];
    const float* glob_vals  = (const float*)d_in[3];
    const int*   tgt_loc    = (const int*)  d_in[4];
    const float* tsdf_loc   = (const float*)d_in[5];
    const int*   tgt_graw   = (const int*)  d_in[6];
    const float* tsdf_glob  = (const float*)d_in[7];
    const int*   origin     = (const int*)  d_in[8];
    float* out = (float*)d_out;

    const int B = 256;
    const int NV4 = (DIM3 * C) / 4;                        /* 5308416 */
    k_init<<<(NV4 + B - 1) / B, B>>>(out, cur_coords);
    k_win_cur_tgt<<<(N_TGT + B - 1) / B, B>>>(cur_coords, tgt_graw, tgt_loc,
                                              origin, out);
    k_win_glob<<<(N_GLOB + B - 1) / B, B>>>(glob_raw, origin, out);
    k_write_vols<<<((N_CUR + N_GLOB) * 6 + B - 1) / B, B>>>(
        cur_coords, cur_vals, glob_raw, origin, glob_vals, out);
    k_write_tgt<<<(N_TGT + B - 1) / B, B>>>(tgt_graw, tgt_loc, origin,
                                            tsdf_glob, tsdf_loc, out);
}

// round 3
// speedup vs baseline: 1.0370x; 1.0370x over previous
#include <cuda_runtime.h>

#define DIM 96
#define DIM3 (DIM*DIM*DIM)            /* 884736 */
#define C 24
#define N_CUR 150000
#define N_GLOB 200000
#define N_TGT_LOC 100000
#define N_TGT_GLOB 120000
#define N_TGT (N_TGT_LOC + N_TGT_GLOB)   /* 220000 */

/* output layout (float32, concat of reference return tuple) */
#define OFF_COORDS 0
#define OFF_CURVOL (N_CUR*3)                      /* 450000 */
#define OFF_GLOBVOL (OFF_CURVOL + DIM3*C)         /* 21683664 */
#define OFF_TGTVOL (OFF_GLOBVOL + DIM3*C)         /* 42917328 */
#define OFF_VALID  (OFF_TGTVOL + DIM3)            /* 43802064 */
#define OFF_VALIDT (OFF_VALID + N_GLOB)           /* 44002064 */
/* total = 44122064 */

__device__ int g_win_cur[DIM3];
__device__ int g_win_glob[DIM3];
__device__ int g_win_tgt[DIM3];

__device__ __forceinline__ int voxel(int x, int y, int z) {
    return (x * DIM + y) * DIM + z;
}

/* ---- 1. small init: winners = -1, coords copy (no volume zero-fill!) ---- */
__global__ void k_init(float* __restrict__ out, const int* __restrict__ cur_coords) {
    int i = blockIdx.x * blockDim.x + threadIdx.x;
    if (i < DIM3 / 4) {                    /* 221184 */
        int4 neg = make_int4(-1, -1, -1, -1);
        ((int4*)g_win_cur)[i]  = neg;
        ((int4*)g_win_glob)[i] = neg;
        ((int4*)g_win_tgt)[i]  = neg;
    }
    if (i < (N_CUR * 3) / 4) {             /* 112500 */
        int4 c = ((const int4*)cur_coords)[i];
        ((float4*)(out + OFF_COORDS))[i] =
            make_float4((float)c.x, (float)c.y, (float)c.z, (float)c.w);
    }
}

/* ---- 2. fused winners: current (last wins) + target (global then local) ---- */
__global__ void k_win_cur_tgt(const int* __restrict__ cc,
                              const int* __restrict__ gtraw,
                              const int* __restrict__ loc,
                              const int* __restrict__ org,
                              float* __restrict__ out) {
    int i = blockIdx.x * blockDim.x + threadIdx.x;
    if (i < N_CUR) {
        int x = cc[3*i], y = cc[3*i+1], z = cc[3*i+2];
        if ((unsigned)x < DIM && (unsigned)y < DIM && (unsigned)z < DIM)
            atomicMax(&g_win_cur[voxel(x, y, z)], i);
    }
    if (i < N_TGT) {
        if (i < N_TGT_GLOB) {
            int x = gtraw[3*i]   - org[0];
            int y = gtraw[3*i+1] - org[1];
            int z = gtraw[3*i+2] - org[2];
            bool inb = (unsigned)x < DIM && (unsigned)y < DIM && (unsigned)z < DIM;
            out[OFF_VALIDT + i] = inb ? 1.f : 0.f;
            if (inb) atomicMax(&g_win_tgt[voxel(x, y, z)], i);
        } else {
            int j = i - N_TGT_GLOB;
            int x = loc[3*j], y = loc[3*j+1], z = loc[3*j+2];
            if ((unsigned)x < DIM && (unsigned)y < DIM && (unsigned)z < DIM)
                atomicMax(&g_win_tgt[voxel(x, y, z)], i);
        }
    }
}

/* ---- 3. global winners: needs occupancy (= g_win_cur >= 0) ---- */
__global__ void k_win_glob(const int* __restrict__ graw,
                           const int* __restrict__ org,
                           float* __restrict__ out) {
    int i = blockIdx.x * blockDim.x + threadIdx.x;
    if (i >= N_GLOB) return;
    int x = graw[3*i]   - org[0];
    int y = graw[3*i+1] - org[1];
    int z = graw[3*i+2] - org[2];
    bool inb = (unsigned)x < DIM && (unsigned)y < DIM && (unsigned)z < DIM;
    int cx = min(max(x, 0), DIM-1);
    int cy = min(max(y, 0), DIM-1);
    int cz = min(max(z, 0), DIM-1);
    bool occ = g_win_cur[voxel(cx, cy, cz)] >= 0;
    bool valid = inb && occ;
    out[OFF_VALID + i] = valid ? 1.f : 0.f;
    if (valid) atomicMax(&g_win_glob[voxel(x, y, z)], i);
}

/* ---- 4. paint: one coalesced pass writing every volume byte exactly once ---- */
__global__ void k_paint(const float* __restrict__ cvals,
                        const float* __restrict__ gvals,
                        const float* __restrict__ gtsdf,
                        const float* __restrict__ ltsdf,
                        float* __restrict__ out) {
    int i = blockIdx.x * blockDim.x + threadIdx.x;
    const int NV4 = (DIM3 * C) / 4;        /* 5308416 */
    if (i < NV4) {
        int v = i / 6, q = i % 6;
        int wc = g_win_cur[v];
        float4 rc = make_float4(0.f, 0.f, 0.f, 0.f);
        if (wc >= 0) rc = ((const float4*)(cvals + wc * C))[q];
        int wg = g_win_glob[v];
        float4 rg = make_float4(0.f, 0.f, 0.f, 0.f);
        if (wg >= 0) rg = ((const float4*)(gvals + wg * C))[q];
        ((float4*)(out + OFF_CURVOL))[i]  = rc;
        ((float4*)(out + OFF_GLOBVOL))[i] = rg;
    }
    if (i < DIM3) {
        int wt = g_win_tgt[i];
        float t = 1.0f;
        if (wt >= 0)
            t = (wt < N_TGT_GLOB) ? gtsdf[wt] : ltsdf[wt - N_TGT_GLOB];
        out[OFF_TGTVOL + i] = t;
    }
}

extern "C" void kernel_launch(void* const* d_in, const int* in_sizes, int n_in,
                              void* d_out, int out_size) {
    const int*   cur_coords = (const int*)  d_in[0];
    const float* cur_vals   = (const float*)d_in[1];
    const int*   glob_raw   = (const int*)  d_in[2];
    const float* glob_vals  = (const float*)d_in[3];
    const int*   tgt_loc    = (const int*)  d_in[4];
    const float* tsdf_loc   = (const float*)d_in[5];
    const int*   tgt_graw   = (const int*)  d_in[6];
    const float* tsdf_glob  = (const float*)d_in[7];
    const int*   origin     = (const int*)  d_in[8];
    float* out = (float*)d_out;

    const int B = 256;
    const int NV4 = (DIM3 * C) / 4;                        /* 5308416 */
    k_init<<<(DIM3 / 4 + B - 1) / B, B>>>(out, cur_coords);
    k_win_cur_tgt<<<(N_TGT + B - 1) / B, B>>>(cur_coords, tgt_graw, tgt_loc,
                                              origin, out);
    k_win_glob<<<(N_GLOB + B - 1) / B, B>>>(glob_raw, origin, out);
    k_paint<<<(NV4 + B - 1) / B, B>>>(cur_vals, glob_vals,
                                      tsdf_glob, tsdf_loc, out);
}

// round 4
// speedup vs baseline: 1.2727x; 1.2273x over previous
#include <cuda_runtime.h>

#define DIM 96
#define DIM3 (DIM*DIM*DIM)            /* 884736 */
#define C 24
#define N_CUR 150000
#define N_GLOB 200000
#define N_TGT_LOC 100000
#define N_TGT_GLOB 120000
#define N_TGT (N_TGT_LOC + N_TGT_GLOB)   /* 220000 */

/* output layout (float32, concat of reference return tuple) */
#define OFF_COORDS 0
#define OFF_CURVOL (N_CUR*3)                      /* 450000 */
#define OFF_GLOBVOL (OFF_CURVOL + DIM3*C)         /* 21683664 */
#define OFF_TGTVOL (OFF_GLOBVOL + DIM3*C)         /* 42917328 */
#define OFF_VALID  (OFF_TGTVOL + DIM3)            /* 43802064 */
#define OFF_VALIDT (OFF_VALID + N_GLOB)           /* 44002064 */
/* total = 44122064 */

#define NV4 ((DIM3 * C) / 4)          /* 5308416 */
#define NV4H (NV4 / 2)                /* 2654208 */

__device__ int g_win_cur[DIM3];
__device__ int g_win_glob[DIM3];
__device__ int g_win_tgt[DIM3];

__device__ __forceinline__ int voxel(int x, int y, int z) {
    return (x * DIM + y) * DIM + z;
}

/* ---- 1. small init: winners = -1, coords copy ---- */
__global__ void k_init(float* __restrict__ out, const int* __restrict__ cur_coords) {
    int i = blockIdx.x * blockDim.x + threadIdx.x;
    if (i < DIM3 / 4) {                    /* 221184 */
        int4 neg = make_int4(-1, -1, -1, -1);
        ((int4*)g_win_cur)[i]  = neg;
        ((int4*)g_win_glob)[i] = neg;
        ((int4*)g_win_tgt)[i]  = neg;
    }
    if (i < (N_CUR * 3) / 4) {             /* 112500 */
        int4 c = ((const int4*)cur_coords)[i];
        float4 f = make_float4((float)c.x, (float)c.y, (float)c.z, (float)c.w);
        __stcs(((float4*)(out + OFF_COORDS)) + i, f);
    }
}

/* ---- 2. fused winners: current (last wins) + target (global then local) ---- */
__global__ void k_win_cur_tgt(const int* __restrict__ cc,
                              const int* __restrict__ gtraw,
                              const int* __restrict__ loc,
                              const int* __restrict__ org,
                              float* __restrict__ out) {
    int i = blockIdx.x * blockDim.x + threadIdx.x;
    if (i < N_CUR) {
        int x = cc[3*i], y = cc[3*i+1], z = cc[3*i+2];
        if ((unsigned)x < DIM && (unsigned)y < DIM && (unsigned)z < DIM)
            atomicMax(&g_win_cur[voxel(x, y, z)], i);
    }
    if (i < N_TGT) {
        if (i < N_TGT_GLOB) {
            int x = gtraw[3*i]   - org[0];
            int y = gtraw[3*i+1] - org[1];
            int z = gtraw[3*i+2] - org[2];
            bool inb = (unsigned)x < DIM && (unsigned)y < DIM && (unsigned)z < DIM;
            out[OFF_VALIDT + i] = inb ? 1.f : 0.f;
            if (inb) atomicMax(&g_win_tgt[voxel(x, y, z)], i);
        } else {
            int j = i - N_TGT_GLOB;
            int x = loc[3*j], y = loc[3*j+1], z = loc[3*j+2];
            if ((unsigned)x < DIM && (unsigned)y < DIM && (unsigned)z < DIM)
                atomicMax(&g_win_tgt[voxel(x, y, z)], i);
        }
    }
}

/* ---- 3. global winners: needs occupancy (= g_win_cur >= 0) ---- */
__global__ void k_win_glob(const int* __restrict__ graw,
                           const int* __restrict__ org,
                           float* __restrict__ out) {
    int i = blockIdx.x * blockDim.x + threadIdx.x;
    if (i >= N_GLOB) return;
    int x = graw[3*i]   - org[0];
    int y = graw[3*i+1] - org[1];
    int z = graw[3*i+2] - org[2];
    bool inb = (unsigned)x < DIM && (unsigned)y < DIM && (unsigned)z < DIM;
    int cx = min(max(x, 0), DIM-1);
    int cy = min(max(y, 0), DIM-1);
    int cz = min(max(z, 0), DIM-1);
    bool occ = g_win_cur[voxel(cx, cy, cz)] >= 0;
    bool valid = inb && occ;
    out[OFF_VALID + i] = valid ? 1.f : 0.f;
    if (valid) atomicMax(&g_win_glob[voxel(x, y, z)], i);
}

/* ---- 4. paint: coalesced, streaming stores, 2 quads/thread for ILP ---- */
__device__ __forceinline__ void paint_quad(int i,
                                           const float* __restrict__ cvals,
                                           const float* __restrict__ gvals,
                                           float* __restrict__ out) {
    int v = i / 6, q = i % 6;
    int wc = __ldg(&g_win_cur[v]);
    int wg = __ldg(&g_win_glob[v]);
    float4 rc = make_float4(0.f, 0.f, 0.f, 0.f);
    float4 rg = make_float4(0.f, 0.f, 0.f, 0.f);
    if (wc >= 0) rc = __ldg(((const float4*)(cvals + wc * C)) + q);
    if (wg >= 0) rg = __ldg(((const float4*)(gvals + wg * C)) + q);
    __stcs(((float4*)(out + OFF_CURVOL))  + i, rc);
    __stcs(((float4*)(out + OFF_GLOBVOL)) + i, rg);
}

__global__ void k_paint(const float* __restrict__ cvals,
                        const float* __restrict__ gvals,
                        const float* __restrict__ gtsdf,
                        const float* __restrict__ ltsdf,
                        float* __restrict__ out) {
    int i = blockIdx.x * blockDim.x + threadIdx.x;
    if (i < NV4H) {
        paint_quad(i, cvals, gvals, out);
        paint_quad(i + NV4H, cvals, gvals, out);
    }
    if (i < DIM3) {
        int wt = __ldg(&g_win_tgt[i]);
        float t = 1.0f;
        if (wt >= 0)
            t = (wt < N_TGT_GLOB) ? __ldg(&gtsdf[wt]) : __ldg(&ltsdf[wt - N_TGT_GLOB]);
        __stcs(out + OFF_TGTVOL + i, t);
    }
}

extern "C" void kernel_launch(void* const* d_in, const int* in_sizes, int n_in,
                              void* d_out, int out_size) {
    const int*   cur_coords = (const int*)  d_in[0];
    const float* cur_vals   = (const float*)d_in[1];
    const int*   glob_raw   = (const int*)  d_in[2];
    const float* glob_vals  = (const float*)d_in[3];
    const int*   tgt_loc    = (const int*)  d_in[4];
    const float* tsdf_loc   = (const float*)d_in[5];
    const int*   tgt_graw   = (const int*)  d_in[6];
    const float* tsdf_glob  = (const float*)d_in[7];
    const int*   origin     = (const int*)  d_in[8];
    float* out = (float*)d_out;

    const int B = 256;
    k_init<<<(DIM3 / 4 + B - 1) / B, B>>>(out, cur_coords);
    k_win_cur_tgt<<<(N_TGT + B - 1) / B, B>>>(cur_coords, tgt_graw, tgt_loc,
                                              origin, out);
    k_win_glob<<<(N_GLOB + B - 1) / B, B>>>(glob_raw, origin, out);
    k_paint<<<(NV4H + B - 1) / B, B>>>(cur_vals, glob_vals,
                                       tsdf_glob, tsdf_loc, out);
}